// round 13
// baseline (speedup 1.0000x reference)
#include <cuda_runtime.h>
#include <cuda_fp16.h>
#include <mma.h>

using namespace nvcuda;

// ---------------------------------------------------------------------------
// GATConv: rst[src] += softmax_dst(leaky_relu(e_l[src]+e_r[dst])) * Zp[dst]
// N=50000, E=1.6M, IN=128, OUT=32, HEADS=4 (OUT*H = 128)
// R4 (134.8us) source, byte-identical, with EXACTLY ONE change:
//   k_gather uses half-warp-per-edge LDG.128 row reads (2 edges per warp-step).
// ---------------------------------------------------------------------------

#define NMAX 50016
#define EMAX 1600000
#define OH 128

// ---- scratch ----------------------------------------------------------------
__device__ __half   g_Zph[(size_t)NMAX * OH];  // projected (then /s) fp16
__device__ float    g_el[NMAX * 4];
__device__ float    g_er[NMAX * 4];
__device__ float    g_s [NMAX * 4];            // softmax denominators
__device__ int      g_deg[NMAX];
__device__ int      g_off[NMAX + 1];
__device__ int      g_cur[NMAX];
__device__ int      g_bsum[128];
__device__ int4     g_slot[EMAX];              // {dst, half2 e01, half2 e23, 0}
__device__ int      g_is64;

// ---- helpers ------------------------------------------------------------------
__device__ __forceinline__ float4 wred_sum(float4 v) {
#pragma unroll
    for (int o = 16; o; o >>= 1) {
        v.x += __shfl_xor_sync(0xffffffffu, v.x, o);
        v.y += __shfl_xor_sync(0xffffffffu, v.y, o);
        v.z += __shfl_xor_sync(0xffffffffu, v.z, o);
        v.w += __shfl_xor_sync(0xffffffffu, v.w, o);
    }
    return v;
}

// ---- detect index width ----------------------------------------------------------
__global__ void k_detect(const int* w) {
    int v = w[2 * threadIdx.x + 1];
    int any = __syncthreads_or(v != 0);
    if (threadIdx.x == 0) g_is64 = !any;
}

// ---- zero accumulators -------------------------------------------------------------
__global__ void k_init(int N) {
    int i = blockIdx.x * blockDim.x + threadIdx.x;
    int stride = gridDim.x * blockDim.x;
    for (int j = i; j < N * 4; j += stride) g_s[j] = 0.0f;
    for (int j = i; j < N; j += stride) g_deg[j] = 0;
}

// ---- histogram of src degrees --------------------------------------------------------
__global__ void k_hist(const void* __restrict__ idx, int E) {
    int e = blockIdx.x * blockDim.x + threadIdx.x;
    if (e >= E) return;
    long long s = g_is64 ? ((const long long*)idx)[e] : (long long)((const int*)idx)[e];
    atomicAdd(&g_deg[(int)s], 1);
}

// ---- scan stage 1 ----------------------------------------------------------------------
__global__ void k_scan1(int N) {
    __shared__ int wsum[8];
    int b = blockIdx.x, t = threadIdx.x;
    int base = b * 1024 + t * 4;
    int sv = 0;
#pragma unroll
    for (int i = 0; i < 4; i++) if (base + i < N) sv += g_deg[base + i];
#pragma unroll
    for (int o = 16; o; o >>= 1) sv += __shfl_xor_sync(0xffffffffu, sv, o);
    if ((t & 31) == 0) wsum[t >> 5] = sv;
    __syncthreads();
    if (t == 0) {
        int tot = 0;
#pragma unroll
        for (int i = 0; i < 8; i++) tot += wsum[i];
        g_bsum[b] = tot;
    }
}

// ---- scan stage 2 ------------------------------------------------------------------------
__global__ void k_scan2(int nb) {
    int s = 0;
    for (int i = 0; i < nb; i++) { int v = g_bsum[i]; g_bsum[i] = s; s += v; }
}

// ---- scan stage 3 -------------------------------------------------------------------------
__global__ void k_scan3(int N, int E) {
    __shared__ int wsum[8];
    int b = blockIdx.x, t = threadIdx.x;
    int lane = t & 31, w = t >> 5;
    int base = b * 1024 + t * 4;
    int v[4];
#pragma unroll
    for (int i = 0; i < 4; i++) v[i] = (base + i < N) ? g_deg[base + i] : 0;
    int tsum = v[0] + v[1] + v[2] + v[3];
    int x = tsum;
#pragma unroll
    for (int o = 1; o < 32; o <<= 1) {
        int y = __shfl_up_sync(0xffffffffu, x, o);
        if (lane >= o) x += y;
    }
    if (lane == 31) wsum[w] = x;
    __syncthreads();
    if (w == 0) {
        int y = (lane < 8) ? wsum[lane] : 0;
#pragma unroll
        for (int o = 1; o < 8; o <<= 1) {
            int z = __shfl_up_sync(0xffffffffu, y, o);
            if (lane >= o) y += z;
        }
        if (lane < 8) wsum[lane] = y;
    }
    __syncthreads();
    int run = x - tsum + (w ? wsum[w - 1] : 0) + g_bsum[b];
#pragma unroll
    for (int i = 0; i < 4; i++) {
        if (base + i < N) { g_off[base + i] = run; g_cur[base + i] = run; }
        run += v[i];
    }
    if (b == 0 && t == 0) g_off[N] = E;
}

// ---- tensor-core GEMM: Zp = Z @ W^T + b (fp16 store), fused e_l/e_r ---------------------
#define GW 136
#define CW 132
#define GEMM_SMEM 52224
__global__ void k_gemm_mma(const float* __restrict__ Z, const float* __restrict__ W,
                           const float* __restrict__ b, const float* __restrict__ al,
                           const float* __restrict__ ar, int N) {
    extern __shared__ char smraw[];
    __half* Wh = (__half*)smraw;
    __half* Zh = (__half*)(smraw + 128 * GW * 2);
    float*  Cs = (float*)smraw;

    const int tid = threadIdx.x;
    const int node0 = blockIdx.x * 64;

    for (int i = tid; i < 128 * 32; i += 256) {
        int c = i >> 5, kq = i & 31;
        float4 w4 = *(const float4*)(W + c * 128 + kq * 4);
        __half2 h0 = __floats2half2_rn(w4.x, w4.y);
        __half2 h1 = __floats2half2_rn(w4.z, w4.w);
        *(uint2*)(Wh + c * GW + kq * 4) =
            make_uint2(*reinterpret_cast<unsigned*>(&h0), *reinterpret_cast<unsigned*>(&h1));
    }
    for (int i = tid; i < 64 * 32; i += 256) {
        int r = i >> 5, kq = i & 31;
        int row = node0 + r; if (row >= N) row = N - 1;
        float4 z4 = *(const float4*)(Z + (size_t)row * 128 + kq * 4);
        __half2 h0 = __floats2half2_rn(z4.x, z4.y);
        __half2 h1 = __floats2half2_rn(z4.z, z4.w);
        *(uint2*)(Zh + r * GW + kq * 4) =
            make_uint2(*reinterpret_cast<unsigned*>(&h0), *reinterpret_cast<unsigned*>(&h1));
    }
    __syncthreads();

    const int w  = tid >> 5;
    const int wr = w >> 1;
    const int wc = w & 1;

    wmma::fragment<wmma::accumulator, 16, 16, 16, float> acc[4];
#pragma unroll
    for (int c = 0; c < 4; c++) wmma::fill_fragment(acc[c], 0.0f);

#pragma unroll
    for (int k = 0; k < 128; k += 16) {
        wmma::fragment<wmma::matrix_a, 16, 16, 16, __half, wmma::row_major> af;
        wmma::load_matrix_sync(af, Zh + (wr * 16) * GW + k, GW);
#pragma unroll
        for (int c = 0; c < 4; c++) {
            wmma::fragment<wmma::matrix_b, 16, 16, 16, __half, wmma::col_major> bf;
            wmma::load_matrix_sync(bf, Wh + (wc * 64 + c * 16) * GW + k, GW);
            wmma::mma_sync(acc[c], af, bf, acc[c]);
        }
    }
    __syncthreads();
#pragma unroll
    for (int c = 0; c < 4; c++)
        wmma::store_matrix_sync(Cs + (wr * 16) * CW + wc * 64 + c * 16, acc[c], CW,
                                wmma::mem_row_major);
    __syncthreads();

    const int lane = tid & 31;
    float4 bb  = *(const float4*)(b  + 4 * lane);
    float4 al4 = *(const float4*)(al + 4 * lane);
    float4 ar4 = *(const float4*)(ar + 4 * lane);

#pragma unroll
    for (int rr = 0; rr < 8; rr++) {
        int r = w * 8 + rr;
        int node = node0 + r;
        float4 v = *(const float4*)(Cs + r * CW + lane * 4);
        v.x += bb.x; v.y += bb.y; v.z += bb.z; v.w += bb.w;
        if (node < N) {
            __half2 h0 = __floats2half2_rn(v.x, v.y);
            __half2 h1 = __floats2half2_rn(v.z, v.w);
            *(uint2*)(g_Zph + (size_t)node * OH + 4 * lane) =
                make_uint2(*reinterpret_cast<unsigned*>(&h0), *reinterpret_cast<unsigned*>(&h1));
        }
        float4 pl = make_float4(v.x * al4.x, v.y * al4.y, v.z * al4.z, v.w * al4.w);
        float4 pr = make_float4(v.x * ar4.x, v.y * ar4.y, v.z * ar4.z, v.w * ar4.w);
        pl = wred_sum(pl);
        pr = wred_sum(pr);
        if (lane == 0 && node < N) {
            *(float4*)(g_el + node * 4) = pl;
            *(float4*)(g_er + node * 4) = pr;
        }
    }
}

// ---- fused edge pass: logits + exp + denom red + direct CSR placement ---------------------
__global__ void k_fused(const void* __restrict__ idx, int E) {
    int e = blockIdx.x * blockDim.x + threadIdx.x;
    if (e >= E) return;
    int is64 = g_is64;
    long long s, d;
    if (is64) {
        s = ((const long long*)idx)[e];
        d = ((const long long*)idx)[E + e];
    } else {
        s = ((const int*)idx)[e];
        d = ((const int*)idx)[E + e];
    }
    float4 l = *(const float4*)(g_el + s * 4);
    float4 r = *(const float4*)(g_er + d * 4);
    float4 a;
    a.x = l.x + r.x; a.x = a.x > 0.f ? a.x : 0.01f * a.x;
    a.y = l.y + r.y; a.y = a.y > 0.f ? a.y : 0.01f * a.y;
    a.z = l.z + r.z; a.z = a.z > 0.f ? a.z : 0.01f * a.z;
    a.w = l.w + r.w; a.w = a.w > 0.f ? a.w : 0.01f * a.w;
    float4 ex;
    ex.x = __expf(a.x); ex.y = __expf(a.y); ex.z = __expf(a.z); ex.w = __expf(a.w);
    float* sb = g_s + d * 4;
    asm volatile("red.global.add.v4.f32 [%0], {%1, %2, %3, %4};"
                 :: "l"(sb), "f"(ex.x), "f"(ex.y), "f"(ex.z), "f"(ex.w) : "memory");
    int pos = atomicAdd(&g_cur[(int)s], 1);
    __half2 h01 = __floats2half2_rn(ex.x, ex.y);
    __half2 h23 = __floats2half2_rn(ex.z, ex.w);
    int4 slot;
    slot.x = (int)d;
    slot.y = *reinterpret_cast<int*>(&h01);
    slot.z = *reinterpret_cast<int*>(&h23);
    slot.w = 0;
    g_slot[pos] = slot;
}

// ---- fold 1/s into Zp --------------------------------------------------------------------
__global__ void k_scale(int N) {
    int t = blockIdx.x * blockDim.x + threadIdx.x;
    int node = t >> 5, lane = t & 31;
    if (node >= N) return;
    float4 s4 = *(const float4*)(g_s + node * 4);
    float ix = __fdividef(1.f, s4.x), iy = __fdividef(1.f, s4.y);
    float iz = __fdividef(1.f, s4.z), iw = __fdividef(1.f, s4.w);
    __half* p = g_Zph + (size_t)node * OH + lane * 4;
    uint2 z = *(uint2*)p;
    float2 lo = __half22float2(*reinterpret_cast<__half2*>(&z.x));
    float2 hi = __half22float2(*reinterpret_cast<__half2*>(&z.y));
    lo.x *= ix; lo.y *= iy; hi.x *= iz; hi.y *= iw;
    __half2 h0 = __floats2half2_rn(lo.x, lo.y);
    __half2 h1 = __floats2half2_rn(hi.x, hi.y);
    *(uint2*)p = make_uint2(*reinterpret_cast<unsigned*>(&h0), *reinterpret_cast<unsigned*>(&h1));
}

// ---- gather-reduce: half-warp per edge, LDG.128 rows, 2 edges per warp-step -------------------
// Lane layout: half = lane>>4 (edge selector), l = lane&15 (column group).
// Lane (half, l) accumulates cols 8l..8l+7 of edge (j+half): acc0 = cols 8l..8l+3,
// acc1 = cols 8l+4..8l+7. Head pattern within 4 consecutive cols is (e0,e1,e2,e3).
// Final: xor-16 shuffle combine, lanes 0-15 store 32B each.
__global__ void k_gather(float* __restrict__ out, int N) {
    int gw = (blockIdx.x * blockDim.x + threadIdx.x) >> 5;
    int lane = threadIdx.x & 31;
    if (gw >= N) return;
    int beg = g_off[gw], end = g_off[gw + 1];
    const int half = lane >> 4;
    const int l = lane & 15;
    float4 acc0 = make_float4(0.f, 0.f, 0.f, 0.f);
    float4 acc1 = make_float4(0.f, 0.f, 0.f, 0.f);
    const __half* zb = g_Zph;

#define ACC8(S, Z)                                                          \
    {                                                                       \
        float2 e01 = __half22float2(*reinterpret_cast<__half2*>(&(S).y));  \
        float2 e23 = __half22float2(*reinterpret_cast<__half2*>(&(S).z));  \
        float2 p0 = __half22float2(*reinterpret_cast<__half2*>(&(Z).x));   \
        float2 p1 = __half22float2(*reinterpret_cast<__half2*>(&(Z).y));   \
        float2 p2 = __half22float2(*reinterpret_cast<__half2*>(&(Z).z));   \
        float2 p3 = __half22float2(*reinterpret_cast<__half2*>(&(Z).w));   \
        acc0.x += e01.x * p0.x;  acc0.y += e01.y * p0.y;                   \
        acc0.z += e23.x * p1.x;  acc0.w += e23.y * p1.y;                   \
        acc1.x += e01.x * p2.x;  acc1.y += e01.y * p2.y;                   \
        acc1.z += e23.x * p3.x;  acc1.w += e23.y * p3.y;                   \
    }

    int j = beg;
    // 4 edges per iteration (2 per warp-step, 2 steps for MLP)
    for (; j + 3 < end; j += 4) {
        int4 sa = g_slot[j + half];
        int4 sb = g_slot[j + 2 + half];
        uint4 za = *(const uint4*)(zb + (size_t)sa.x * OH + l * 8);
        uint4 zc = *(const uint4*)(zb + (size_t)sb.x * OH + l * 8);
        ACC8(sa, za);
        ACC8(sb, zc);
    }
    for (; j + 1 < end; j += 2) {
        int4 sa = g_slot[j + half];
        uint4 za = *(const uint4*)(zb + (size_t)sa.x * OH + l * 8);
        ACC8(sa, za);
    }
    if (j < end && half == 0) {
        int4 sa = g_slot[j];
        uint4 za = *(const uint4*)(zb + (size_t)sa.x * OH + l * 8);
        ACC8(sa, za);
    }
#undef ACC8

    // combine the two half-warp accumulator sets (lane k <-> lane k+16)
    acc0.x += __shfl_xor_sync(0xffffffffu, acc0.x, 16);
    acc0.y += __shfl_xor_sync(0xffffffffu, acc0.y, 16);
    acc0.z += __shfl_xor_sync(0xffffffffu, acc0.z, 16);
    acc0.w += __shfl_xor_sync(0xffffffffu, acc0.w, 16);
    acc1.x += __shfl_xor_sync(0xffffffffu, acc1.x, 16);
    acc1.y += __shfl_xor_sync(0xffffffffu, acc1.y, 16);
    acc1.z += __shfl_xor_sync(0xffffffffu, acc1.z, 16);
    acc1.w += __shfl_xor_sync(0xffffffffu, acc1.w, 16);

    if (half == 0) {
        float* op = out + (size_t)gw * OH + l * 8;
        *(float4*)(op)     = acc0;
        *(float4*)(op + 4) = acc1;
    }
}

// ---- second stream for capture fork ------------------------------------------------------------
struct StreamHolder {
    cudaStream_t s2 = nullptr;
    cudaEvent_t evF = nullptr, evJ = nullptr;
    bool ok = false;
    StreamHolder() {
        ok = (cudaStreamCreateWithFlags(&s2, cudaStreamNonBlocking) == cudaSuccess) &&
             (cudaEventCreateWithFlags(&evF, cudaEventDisableTiming) == cudaSuccess) &&
             (cudaEventCreateWithFlags(&evJ, cudaEventDisableTiming) == cudaSuccess);
    }
};
static StreamHolder g_sh;

// ---- launch --------------------------------------------------------------------------------------
extern "C" void kernel_launch(void* const* d_in, const int* in_sizes, int n_in,
                              void* d_out, int out_size) {
    const void*  idx = d_in[0];
    const float* Z   = (const float*)d_in[2];
    const float* W   = (const float*)d_in[3];
    const float* b   = (const float*)d_in[4];
    const float* al  = (const float*)d_in[5];
    const float* ar  = (const float*)d_in[6];
    float* out = (float*)d_out;

    int E = in_sizes[0] / 2;
    int N = in_sizes[2] / 128;
    int nb = (N + 1023) / 1024;
    int eb = (E + 255) / 256;

    k_detect<<<1, 512>>>((const int*)idx);

    bool fork = g_sh.ok;
    cudaStream_t sb = fork ? g_sh.s2 : (cudaStream_t)0;
    if (fork) {
        cudaEventRecord(g_sh.evF, 0);
        cudaStreamWaitEvent(sb, g_sh.evF, 0);
    }
    // index-side chain
    k_init <<<256, 256, 0, sb>>>(N);
    k_hist <<<eb, 256, 0, sb>>>(idx, E);
    k_scan1<<<nb, 256, 0, sb>>>(N);
    k_scan2<<<1, 1, 0, sb>>>(nb);
    k_scan3<<<nb, 256, 0, sb>>>(N, E);

    // feature-side GEMM (concurrent with index chain)
    cudaFuncSetAttribute(k_gemm_mma, cudaFuncAttributeMaxDynamicSharedMemorySize, GEMM_SMEM);
    k_gemm_mma<<<(N + 63) / 64, 256, GEMM_SMEM>>>(Z, W, b, al, ar, N);

    if (fork) {
        cudaEventRecord(g_sh.evJ, sb);
        cudaStreamWaitEvent(0, g_sh.evJ, 0);
    }

    k_fused<<<eb, 256>>>(idx, E);
    k_scale<<<(N * 32 + 255) / 256, 256>>>(N);
    k_gather<<<(N * 32 + 255) / 256, 256>>>(out, N);
}

// round 14
// speedup vs baseline: 1.0743x; 1.0743x over previous
#include <cuda_runtime.h>
#include <cuda_fp16.h>
#include <mma.h>

using namespace nvcuda;

// ---------------------------------------------------------------------------
// GATConv: rst[src] += softmax_dst(leaky_relu(e_l[src]+e_r[dst])) * Zp[dst]
// N=50000, E=1.6M, IN=128, OUT=32, HEADS=4 (OUT*H = 128)
// R4 (134.8us) source, byte-identical, with EXACTLY ONE change:
//   k_fused processes 2 edges per thread (vector index loads, 2x MLP).
// ---------------------------------------------------------------------------

#define NMAX 50016
#define EMAX 1600000
#define OH 128

// ---- scratch ----------------------------------------------------------------
__device__ __half   g_Zph[(size_t)NMAX * OH];  // projected (then /s) fp16
__device__ float    g_el[NMAX * 4];
__device__ float    g_er[NMAX * 4];
__device__ float    g_s [NMAX * 4];            // softmax denominators
__device__ int      g_deg[NMAX];
__device__ int      g_off[NMAX + 1];
__device__ int      g_cur[NMAX];
__device__ int      g_bsum[128];
__device__ int4     g_slot[EMAX];              // {dst, half2 e01, half2 e23, 0}
__device__ int      g_is64;

// ---- helpers ------------------------------------------------------------------
__device__ __forceinline__ float4 wred_sum(float4 v) {
#pragma unroll
    for (int o = 16; o; o >>= 1) {
        v.x += __shfl_xor_sync(0xffffffffu, v.x, o);
        v.y += __shfl_xor_sync(0xffffffffu, v.y, o);
        v.z += __shfl_xor_sync(0xffffffffu, v.z, o);
        v.w += __shfl_xor_sync(0xffffffffu, v.w, o);
    }
    return v;
}

// ---- detect index width ----------------------------------------------------------
__global__ void k_detect(const int* w) {
    int v = w[2 * threadIdx.x + 1];
    int any = __syncthreads_or(v != 0);
    if (threadIdx.x == 0) g_is64 = !any;
}

// ---- zero accumulators -------------------------------------------------------------
__global__ void k_init(int N) {
    int i = blockIdx.x * blockDim.x + threadIdx.x;
    int stride = gridDim.x * blockDim.x;
    for (int j = i; j < N * 4; j += stride) g_s[j] = 0.0f;
    for (int j = i; j < N; j += stride) g_deg[j] = 0;
}

// ---- histogram of src degrees --------------------------------------------------------
__global__ void k_hist(const void* __restrict__ idx, int E) {
    int e = blockIdx.x * blockDim.x + threadIdx.x;
    if (e >= E) return;
    long long s = g_is64 ? ((const long long*)idx)[e] : (long long)((const int*)idx)[e];
    atomicAdd(&g_deg[(int)s], 1);
}

// ---- scan stage 1 ----------------------------------------------------------------------
__global__ void k_scan1(int N) {
    __shared__ int wsum[8];
    int b = blockIdx.x, t = threadIdx.x;
    int base = b * 1024 + t * 4;
    int sv = 0;
#pragma unroll
    for (int i = 0; i < 4; i++) if (base + i < N) sv += g_deg[base + i];
#pragma unroll
    for (int o = 16; o; o >>= 1) sv += __shfl_xor_sync(0xffffffffu, sv, o);
    if ((t & 31) == 0) wsum[t >> 5] = sv;
    __syncthreads();
    if (t == 0) {
        int tot = 0;
#pragma unroll
        for (int i = 0; i < 8; i++) tot += wsum[i];
        g_bsum[b] = tot;
    }
}

// ---- scan stage 2 ------------------------------------------------------------------------
__global__ void k_scan2(int nb) {
    int s = 0;
    for (int i = 0; i < nb; i++) { int v = g_bsum[i]; g_bsum[i] = s; s += v; }
}

// ---- scan stage 3 -------------------------------------------------------------------------
__global__ void k_scan3(int N, int E) {
    __shared__ int wsum[8];
    int b = blockIdx.x, t = threadIdx.x;
    int lane = t & 31, w = t >> 5;
    int base = b * 1024 + t * 4;
    int v[4];
#pragma unroll
    for (int i = 0; i < 4; i++) v[i] = (base + i < N) ? g_deg[base + i] : 0;
    int tsum = v[0] + v[1] + v[2] + v[3];
    int x = tsum;
#pragma unroll
    for (int o = 1; o < 32; o <<= 1) {
        int y = __shfl_up_sync(0xffffffffu, x, o);
        if (lane >= o) x += y;
    }
    if (lane == 31) wsum[w] = x;
    __syncthreads();
    if (w == 0) {
        int y = (lane < 8) ? wsum[lane] : 0;
#pragma unroll
        for (int o = 1; o < 8; o <<= 1) {
            int z = __shfl_up_sync(0xffffffffu, y, o);
            if (lane >= o) y += z;
        }
        if (lane < 8) wsum[lane] = y;
    }
    __syncthreads();
    int run = x - tsum + (w ? wsum[w - 1] : 0) + g_bsum[b];
#pragma unroll
    for (int i = 0; i < 4; i++) {
        if (base + i < N) { g_off[base + i] = run; g_cur[base + i] = run; }
        run += v[i];
    }
    if (b == 0 && t == 0) g_off[N] = E;
}

// ---- tensor-core GEMM: Zp = Z @ W^T + b (fp16 store), fused e_l/e_r ---------------------
#define GW 136
#define CW 132
#define GEMM_SMEM 52224
__global__ void k_gemm_mma(const float* __restrict__ Z, const float* __restrict__ W,
                           const float* __restrict__ b, const float* __restrict__ al,
                           const float* __restrict__ ar, int N) {
    extern __shared__ char smraw[];
    __half* Wh = (__half*)smraw;
    __half* Zh = (__half*)(smraw + 128 * GW * 2);
    float*  Cs = (float*)smraw;

    const int tid = threadIdx.x;
    const int node0 = blockIdx.x * 64;

    for (int i = tid; i < 128 * 32; i += 256) {
        int c = i >> 5, kq = i & 31;
        float4 w4 = *(const float4*)(W + c * 128 + kq * 4);
        __half2 h0 = __floats2half2_rn(w4.x, w4.y);
        __half2 h1 = __floats2half2_rn(w4.z, w4.w);
        *(uint2*)(Wh + c * GW + kq * 4) =
            make_uint2(*reinterpret_cast<unsigned*>(&h0), *reinterpret_cast<unsigned*>(&h1));
    }
    for (int i = tid; i < 64 * 32; i += 256) {
        int r = i >> 5, kq = i & 31;
        int row = node0 + r; if (row >= N) row = N - 1;
        float4 z4 = *(const float4*)(Z + (size_t)row * 128 + kq * 4);
        __half2 h0 = __floats2half2_rn(z4.x, z4.y);
        __half2 h1 = __floats2half2_rn(z4.z, z4.w);
        *(uint2*)(Zh + r * GW + kq * 4) =
            make_uint2(*reinterpret_cast<unsigned*>(&h0), *reinterpret_cast<unsigned*>(&h1));
    }
    __syncthreads();

    const int w  = tid >> 5;
    const int wr = w >> 1;
    const int wc = w & 1;

    wmma::fragment<wmma::accumulator, 16, 16, 16, float> acc[4];
#pragma unroll
    for (int c = 0; c < 4; c++) wmma::fill_fragment(acc[c], 0.0f);

#pragma unroll
    for (int k = 0; k < 128; k += 16) {
        wmma::fragment<wmma::matrix_a, 16, 16, 16, __half, wmma::row_major> af;
        wmma::load_matrix_sync(af, Zh + (wr * 16) * GW + k, GW);
#pragma unroll
        for (int c = 0; c < 4; c++) {
            wmma::fragment<wmma::matrix_b, 16, 16, 16, __half, wmma::col_major> bf;
            wmma::load_matrix_sync(bf, Wh + (wc * 64 + c * 16) * GW + k, GW);
            wmma::mma_sync(acc[c], af, bf, acc[c]);
        }
    }
    __syncthreads();
#pragma unroll
    for (int c = 0; c < 4; c++)
        wmma::store_matrix_sync(Cs + (wr * 16) * CW + wc * 64 + c * 16, acc[c], CW,
                                wmma::mem_row_major);
    __syncthreads();

    const int lane = tid & 31;
    float4 bb  = *(const float4*)(b  + 4 * lane);
    float4 al4 = *(const float4*)(al + 4 * lane);
    float4 ar4 = *(const float4*)(ar + 4 * lane);

#pragma unroll
    for (int rr = 0; rr < 8; rr++) {
        int r = w * 8 + rr;
        int node = node0 + r;
        float4 v = *(const float4*)(Cs + r * CW + lane * 4);
        v.x += bb.x; v.y += bb.y; v.z += bb.z; v.w += bb.w;
        if (node < N) {
            __half2 h0 = __floats2half2_rn(v.x, v.y);
            __half2 h1 = __floats2half2_rn(v.z, v.w);
            *(uint2*)(g_Zph + (size_t)node * OH + 4 * lane) =
                make_uint2(*reinterpret_cast<unsigned*>(&h0), *reinterpret_cast<unsigned*>(&h1));
        }
        float4 pl = make_float4(v.x * al4.x, v.y * al4.y, v.z * al4.z, v.w * al4.w);
        float4 pr = make_float4(v.x * ar4.x, v.y * ar4.y, v.z * ar4.z, v.w * ar4.w);
        pl = wred_sum(pl);
        pr = wred_sum(pr);
        if (lane == 0 && node < N) {
            *(float4*)(g_el + node * 4) = pl;
            *(float4*)(g_er + node * 4) = pr;
        }
    }
}

// ---- fused edge pass: 2 edges/thread, vector index loads, ILP-2 ---------------------------
__device__ __forceinline__ void edge_work(int s, int d,
                                          const float4 l, const float4 r) {
    float4 a;
    a.x = l.x + r.x; a.x = a.x > 0.f ? a.x : 0.01f * a.x;
    a.y = l.y + r.y; a.y = a.y > 0.f ? a.y : 0.01f * a.y;
    a.z = l.z + r.z; a.z = a.z > 0.f ? a.z : 0.01f * a.z;
    a.w = l.w + r.w; a.w = a.w > 0.f ? a.w : 0.01f * a.w;
    float4 ex;
    ex.x = __expf(a.x); ex.y = __expf(a.y); ex.z = __expf(a.z); ex.w = __expf(a.w);
    float* sb = g_s + d * 4;
    asm volatile("red.global.add.v4.f32 [%0], {%1, %2, %3, %4};"
                 :: "l"(sb), "f"(ex.x), "f"(ex.y), "f"(ex.z), "f"(ex.w) : "memory");
    int pos = atomicAdd(&g_cur[s], 1);
    __half2 h01 = __floats2half2_rn(ex.x, ex.y);
    __half2 h23 = __floats2half2_rn(ex.z, ex.w);
    int4 slot;
    slot.x = d;
    slot.y = *reinterpret_cast<int*>(&h01);
    slot.z = *reinterpret_cast<int*>(&h23);
    slot.w = 0;
    g_slot[pos] = slot;
}

__global__ void k_fused(const void* __restrict__ idx, int E) {
    int e0 = (blockIdx.x * blockDim.x + threadIdx.x) * 2;
    if (e0 >= E) return;
    bool two = (e0 + 1 < E);
    int s0, s1, d0, d1;
    if (g_is64) {
        longlong2 sp = *(const longlong2*)((const long long*)idx + e0);
        longlong2 dp = *(const longlong2*)((const long long*)idx + E + e0);
        s0 = (int)sp.x; s1 = (int)sp.y; d0 = (int)dp.x; d1 = (int)dp.y;
    } else {
        int2 sp = *(const int2*)((const int*)idx + e0);
        int2 dp = *(const int2*)((const int*)idx + E + e0);
        s0 = sp.x; s1 = sp.y; d0 = dp.x; d1 = dp.y;
    }
    if (!two) { s1 = s0; d1 = d0; }
    // issue all four gathers up front (independent; 2x MLP vs 1-edge version)
    float4 l0 = *(const float4*)(g_el + s0 * 4);
    float4 r0 = *(const float4*)(g_er + d0 * 4);
    float4 l1 = *(const float4*)(g_el + s1 * 4);
    float4 r1 = *(const float4*)(g_er + d1 * 4);
    edge_work(s0, d0, l0, r0);
    if (two) edge_work(s1, d1, l1, r1);
}

// ---- fold 1/s into Zp --------------------------------------------------------------------
__global__ void k_scale(int N) {
    int t = blockIdx.x * blockDim.x + threadIdx.x;
    int node = t >> 5, lane = t & 31;
    if (node >= N) return;
    float4 s4 = *(const float4*)(g_s + node * 4);
    float ix = __fdividef(1.f, s4.x), iy = __fdividef(1.f, s4.y);
    float iz = __fdividef(1.f, s4.z), iw = __fdividef(1.f, s4.w);
    __half* p = g_Zph + (size_t)node * OH + lane * 4;
    uint2 z = *(uint2*)p;
    float2 lo = __half22float2(*reinterpret_cast<__half2*>(&z.x));
    float2 hi = __half22float2(*reinterpret_cast<__half2*>(&z.y));
    lo.x *= ix; lo.y *= iy; hi.x *= iz; hi.y *= iw;
    __half2 h0 = __floats2half2_rn(lo.x, lo.y);
    __half2 h1 = __floats2half2_rn(hi.x, hi.y);
    *(uint2*)p = make_uint2(*reinterpret_cast<unsigned*>(&h0), *reinterpret_cast<unsigned*>(&h1));
}

// ---- gather-reduce: one warp per node, 4x unrolled (proven form) -----------------------------
__global__ void k_gather(float* __restrict__ out, int N) {
    int gw = (blockIdx.x * blockDim.x + threadIdx.x) >> 5;
    int lane = threadIdx.x & 31;
    if (gw >= N) return;
    int beg = g_off[gw], end = g_off[gw + 1];
    float4 acc = make_float4(0.f, 0.f, 0.f, 0.f);
    const __half* zb = g_Zph;
    int j = beg;
    for (; j + 3 < end; j += 4) {
        int4 s0 = g_slot[j];
        int4 s1 = g_slot[j + 1];
        int4 s2 = g_slot[j + 2];
        int4 s3 = g_slot[j + 3];
        uint2 z0 = *(const uint2*)(zb + (size_t)s0.x * OH + lane * 4);
        uint2 z1 = *(const uint2*)(zb + (size_t)s1.x * OH + lane * 4);
        uint2 z2 = *(const uint2*)(zb + (size_t)s2.x * OH + lane * 4);
        uint2 z3 = *(const uint2*)(zb + (size_t)s3.x * OH + lane * 4);
#define ACC(S, Z0, Z1)                                                    \
        {                                                                 \
            float2 e01 = __half22float2(*reinterpret_cast<__half2*>(&S.y));\
            float2 e23 = __half22float2(*reinterpret_cast<__half2*>(&S.z));\
            float2 a0 = __half22float2(*reinterpret_cast<__half2*>(&Z0)); \
            float2 a1 = __half22float2(*reinterpret_cast<__half2*>(&Z1)); \
            acc.x += e01.x * a0.x;  acc.y += e01.y * a0.y;                \
            acc.z += e23.x * a1.x;  acc.w += e23.y * a1.y;                \
        }
        ACC(s0, z0.x, z0.y); ACC(s1, z1.x, z1.y);
        ACC(s2, z2.x, z2.y); ACC(s3, z3.x, z3.y);
    }
    for (; j < end; j++) {
        int4 s0 = g_slot[j];
        uint2 z0 = *(const uint2*)(zb + (size_t)s0.x * OH + lane * 4);
        ACC(s0, z0.x, z0.y);
    }
#undef ACC
    *(float4*)(out + (size_t)gw * OH + lane * 4) = acc;
}

// ---- second stream for capture fork ------------------------------------------------------------
struct StreamHolder {
    cudaStream_t s2 = nullptr;
    cudaEvent_t evF = nullptr, evJ = nullptr;
    bool ok = false;
    StreamHolder() {
        ok = (cudaStreamCreateWithFlags(&s2, cudaStreamNonBlocking) == cudaSuccess) &&
             (cudaEventCreateWithFlags(&evF, cudaEventDisableTiming) == cudaSuccess) &&
             (cudaEventCreateWithFlags(&evJ, cudaEventDisableTiming) == cudaSuccess);
    }
};
static StreamHolder g_sh;

// ---- launch --------------------------------------------------------------------------------------
extern "C" void kernel_launch(void* const* d_in, const int* in_sizes, int n_in,
                              void* d_out, int out_size) {
    const void*  idx = d_in[0];
    const float* Z   = (const float*)d_in[2];
    const float* W   = (const float*)d_in[3];
    const float* b   = (const float*)d_in[4];
    const float* al  = (const float*)d_in[5];
    const float* ar  = (const float*)d_in[6];
    float* out = (float*)d_out;

    int E = in_sizes[0] / 2;
    int N = in_sizes[2] / 128;
    int nb = (N + 1023) / 1024;
    int eb = (E + 255) / 256;

    k_detect<<<1, 512>>>((const int*)idx);

    bool fork = g_sh.ok;
    cudaStream_t sb = fork ? g_sh.s2 : (cudaStream_t)0;
    if (fork) {
        cudaEventRecord(g_sh.evF, 0);
        cudaStreamWaitEvent(sb, g_sh.evF, 0);
    }
    // index-side chain
    k_init <<<256, 256, 0, sb>>>(N);
    k_hist <<<eb, 256, 0, sb>>>(idx, E);
    k_scan1<<<nb, 256, 0, sb>>>(N);
    k_scan2<<<1, 1, 0, sb>>>(nb);
    k_scan3<<<nb, 256, 0, sb>>>(N, E);

    // feature-side GEMM (concurrent with index chain)
    cudaFuncSetAttribute(k_gemm_mma, cudaFuncAttributeMaxDynamicSharedMemorySize, GEMM_SMEM);
    k_gemm_mma<<<(N + 63) / 64, 256, GEMM_SMEM>>>(Z, W, b, al, ar, N);

    if (fork) {
        cudaEventRecord(g_sh.evJ, sb);
        cudaStreamWaitEvent(0, g_sh.evJ, 0);
    }

    k_fused<<<(E + 511) / 512, 256>>>(idx, E);
    k_scale<<<(N * 32 + 255) / 256, 256>>>(N);
    k_gather<<<(N * 32 + 255) / 256, 256>>>(out, N);
}

// round 15
// speedup vs baseline: 1.0906x; 1.0151x over previous
#include <cuda_runtime.h>
#include <cuda_fp16.h>
#include <mma.h>

using namespace nvcuda;

// ---------------------------------------------------------------------------
// GATConv: rst[src] += softmax_dst(leaky_relu(e_l[src]+e_r[dst])) * Zp[dst]
// N=50000, E=1.6M, IN=128, OUT=32, HEADS=4 (OUT*H = 128)
// FINAL: the verified-best R4 configuration (134.8us), byte-identical.
// Pipeline:
//   stream B (side): init -> hist(src) -> 3-stage scan  (~29us, hidden)
//   stream A (main): detect -> tensor-core GEMM (Zp fp16 + fused e_l/e_r)
//   join -> fused edge pass (exp + denom red.v4 + direct CSR placement)
//        -> fold 1/s into Zp -> warp-per-node gather (4x unroll, fp32 accum)
// ---------------------------------------------------------------------------

#define NMAX 50016
#define EMAX 1600000
#define OH 128

// ---- scratch ----------------------------------------------------------------
__device__ __half   g_Zph[(size_t)NMAX * OH];  // projected (then /s) fp16
__device__ float    g_el[NMAX * 4];
__device__ float    g_er[NMAX * 4];
__device__ float    g_s [NMAX * 4];            // softmax denominators
__device__ int      g_deg[NMAX];
__device__ int      g_off[NMAX + 1];
__device__ int      g_cur[NMAX];
__device__ int      g_bsum[128];
__device__ int4     g_slot[EMAX];              // {dst, half2 e01, half2 e23, 0}
__device__ int      g_is64;

// ---- helpers ------------------------------------------------------------------
__device__ __forceinline__ float4 wred_sum(float4 v) {
#pragma unroll
    for (int o = 16; o; o >>= 1) {
        v.x += __shfl_xor_sync(0xffffffffu, v.x, o);
        v.y += __shfl_xor_sync(0xffffffffu, v.y, o);
        v.z += __shfl_xor_sync(0xffffffffu, v.z, o);
        v.w += __shfl_xor_sync(0xffffffffu, v.w, o);
    }
    return v;
}

// ---- detect index width ----------------------------------------------------------
__global__ void k_detect(const int* w) {
    int v = w[2 * threadIdx.x + 1];
    int any = __syncthreads_or(v != 0);
    if (threadIdx.x == 0) g_is64 = !any;
}

// ---- zero accumulators -------------------------------------------------------------
__global__ void k_init(int N) {
    int i = blockIdx.x * blockDim.x + threadIdx.x;
    int stride = gridDim.x * blockDim.x;
    for (int j = i; j < N * 4; j += stride) g_s[j] = 0.0f;
    for (int j = i; j < N; j += stride) g_deg[j] = 0;
}

// ---- histogram of src degrees --------------------------------------------------------
__global__ void k_hist(const void* __restrict__ idx, int E) {
    int e = blockIdx.x * blockDim.x + threadIdx.x;
    if (e >= E) return;
    long long s = g_is64 ? ((const long long*)idx)[e] : (long long)((const int*)idx)[e];
    atomicAdd(&g_deg[(int)s], 1);
}

// ---- scan stage 1 ----------------------------------------------------------------------
__global__ void k_scan1(int N) {
    __shared__ int wsum[8];
    int b = blockIdx.x, t = threadIdx.x;
    int base = b * 1024 + t * 4;
    int sv = 0;
#pragma unroll
    for (int i = 0; i < 4; i++) if (base + i < N) sv += g_deg[base + i];
#pragma unroll
    for (int o = 16; o; o >>= 1) sv += __shfl_xor_sync(0xffffffffu, sv, o);
    if ((t & 31) == 0) wsum[t >> 5] = sv;
    __syncthreads();
    if (t == 0) {
        int tot = 0;
#pragma unroll
        for (int i = 0; i < 8; i++) tot += wsum[i];
        g_bsum[b] = tot;
    }
}

// ---- scan stage 2 ------------------------------------------------------------------------
__global__ void k_scan2(int nb) {
    int s = 0;
    for (int i = 0; i < nb; i++) { int v = g_bsum[i]; g_bsum[i] = s; s += v; }
}

// ---- scan stage 3 -------------------------------------------------------------------------
__global__ void k_scan3(int N, int E) {
    __shared__ int wsum[8];
    int b = blockIdx.x, t = threadIdx.x;
    int lane = t & 31, w = t >> 5;
    int base = b * 1024 + t * 4;
    int v[4];
#pragma unroll
    for (int i = 0; i < 4; i++) v[i] = (base + i < N) ? g_deg[base + i] : 0;
    int tsum = v[0] + v[1] + v[2] + v[3];
    int x = tsum;
#pragma unroll
    for (int o = 1; o < 32; o <<= 1) {
        int y = __shfl_up_sync(0xffffffffu, x, o);
        if (lane >= o) x += y;
    }
    if (lane == 31) wsum[w] = x;
    __syncthreads();
    if (w == 0) {
        int y = (lane < 8) ? wsum[lane] : 0;
#pragma unroll
        for (int o = 1; o < 8; o <<= 1) {
            int z = __shfl_up_sync(0xffffffffu, y, o);
            if (lane >= o) y += z;
        }
        if (lane < 8) wsum[lane] = y;
    }
    __syncthreads();
    int run = x - tsum + (w ? wsum[w - 1] : 0) + g_bsum[b];
#pragma unroll
    for (int i = 0; i < 4; i++) {
        if (base + i < N) { g_off[base + i] = run; g_cur[base + i] = run; }
        run += v[i];
    }
    if (b == 0 && t == 0) g_off[N] = E;
}

// ---- tensor-core GEMM: Zp = Z @ W^T + b (fp16 store), fused e_l/e_r ---------------------
#define GW 136
#define CW 132
#define GEMM_SMEM 52224
__global__ void k_gemm_mma(const float* __restrict__ Z, const float* __restrict__ W,
                           const float* __restrict__ b, const float* __restrict__ al,
                           const float* __restrict__ ar, int N) {
    extern __shared__ char smraw[];
    __half* Wh = (__half*)smraw;
    __half* Zh = (__half*)(smraw + 128 * GW * 2);
    float*  Cs = (float*)smraw;

    const int tid = threadIdx.x;
    const int node0 = blockIdx.x * 64;

    for (int i = tid; i < 128 * 32; i += 256) {
        int c = i >> 5, kq = i & 31;
        float4 w4 = *(const float4*)(W + c * 128 + kq * 4);
        __half2 h0 = __floats2half2_rn(w4.x, w4.y);
        __half2 h1 = __floats2half2_rn(w4.z, w4.w);
        *(uint2*)(Wh + c * GW + kq * 4) =
            make_uint2(*reinterpret_cast<unsigned*>(&h0), *reinterpret_cast<unsigned*>(&h1));
    }
    for (int i = tid; i < 64 * 32; i += 256) {
        int r = i >> 5, kq = i & 31;
        int row = node0 + r; if (row >= N) row = N - 1;
        float4 z4 = *(const float4*)(Z + (size_t)row * 128 + kq * 4);
        __half2 h0 = __floats2half2_rn(z4.x, z4.y);
        __half2 h1 = __floats2half2_rn(z4.z, z4.w);
        *(uint2*)(Zh + r * GW + kq * 4) =
            make_uint2(*reinterpret_cast<unsigned*>(&h0), *reinterpret_cast<unsigned*>(&h1));
    }
    __syncthreads();

    const int w  = tid >> 5;
    const int wr = w >> 1;
    const int wc = w & 1;

    wmma::fragment<wmma::accumulator, 16, 16, 16, float> acc[4];
#pragma unroll
    for (int c = 0; c < 4; c++) wmma::fill_fragment(acc[c], 0.0f);

#pragma unroll
    for (int k = 0; k < 128; k += 16) {
        wmma::fragment<wmma::matrix_a, 16, 16, 16, __half, wmma::row_major> af;
        wmma::load_matrix_sync(af, Zh + (wr * 16) * GW + k, GW);
#pragma unroll
        for (int c = 0; c < 4; c++) {
            wmma::fragment<wmma::matrix_b, 16, 16, 16, __half, wmma::col_major> bf;
            wmma::load_matrix_sync(bf, Wh + (wc * 64 + c * 16) * GW + k, GW);
            wmma::mma_sync(acc[c], af, bf, acc[c]);
        }
    }
    __syncthreads();
#pragma unroll
    for (int c = 0; c < 4; c++)
        wmma::store_matrix_sync(Cs + (wr * 16) * CW + wc * 64 + c * 16, acc[c], CW,
                                wmma::mem_row_major);
    __syncthreads();

    const int lane = tid & 31;
    float4 bb  = *(const float4*)(b  + 4 * lane);
    float4 al4 = *(const float4*)(al + 4 * lane);
    float4 ar4 = *(const float4*)(ar + 4 * lane);

#pragma unroll
    for (int rr = 0; rr < 8; rr++) {
        int r = w * 8 + rr;
        int node = node0 + r;
        float4 v = *(const float4*)(Cs + r * CW + lane * 4);
        v.x += bb.x; v.y += bb.y; v.z += bb.z; v.w += bb.w;
        if (node < N) {
            __half2 h0 = __floats2half2_rn(v.x, v.y);
            __half2 h1 = __floats2half2_rn(v.z, v.w);
            *(uint2*)(g_Zph + (size_t)node * OH + 4 * lane) =
                make_uint2(*reinterpret_cast<unsigned*>(&h0), *reinterpret_cast<unsigned*>(&h1));
        }
        float4 pl = make_float4(v.x * al4.x, v.y * al4.y, v.z * al4.z, v.w * al4.w);
        float4 pr = make_float4(v.x * ar4.x, v.y * ar4.y, v.z * ar4.z, v.w * ar4.w);
        pl = wred_sum(pl);
        pr = wred_sum(pr);
        if (lane == 0 && node < N) {
            *(float4*)(g_el + node * 4) = pl;
            *(float4*)(g_er + node * 4) = pr;
        }
    }
}

// ---- fused edge pass: logits + exp + denom red + direct CSR placement ---------------------
__global__ void k_fused(const void* __restrict__ idx, int E) {
    int e = blockIdx.x * blockDim.x + threadIdx.x;
    if (e >= E) return;
    int is64 = g_is64;
    long long s, d;
    if (is64) {
        s = ((const long long*)idx)[e];
        d = ((const long long*)idx)[E + e];
    } else {
        s = ((const int*)idx)[e];
        d = ((const int*)idx)[E + e];
    }
    float4 l = *(const float4*)(g_el + s * 4);
    float4 r = *(const float4*)(g_er + d * 4);
    float4 a;
    a.x = l.x + r.x; a.x = a.x > 0.f ? a.x : 0.01f * a.x;
    a.y = l.y + r.y; a.y = a.y > 0.f ? a.y : 0.01f * a.y;
    a.z = l.z + r.z; a.z = a.z > 0.f ? a.z : 0.01f * a.z;
    a.w = l.w + r.w; a.w = a.w > 0.f ? a.w : 0.01f * a.w;
    float4 ex;
    ex.x = __expf(a.x); ex.y = __expf(a.y); ex.z = __expf(a.z); ex.w = __expf(a.w);
    float* sb = g_s + d * 4;
    asm volatile("red.global.add.v4.f32 [%0], {%1, %2, %3, %4};"
                 :: "l"(sb), "f"(ex.x), "f"(ex.y), "f"(ex.z), "f"(ex.w) : "memory");
    int pos = atomicAdd(&g_cur[(int)s], 1);
    __half2 h01 = __floats2half2_rn(ex.x, ex.y);
    __half2 h23 = __floats2half2_rn(ex.z, ex.w);
    int4 slot;
    slot.x = (int)d;
    slot.y = *reinterpret_cast<int*>(&h01);
    slot.z = *reinterpret_cast<int*>(&h23);
    slot.w = 0;
    g_slot[pos] = slot;
}

// ---- fold 1/s into Zp --------------------------------------------------------------------
__global__ void k_scale(int N) {
    int t = blockIdx.x * blockDim.x + threadIdx.x;
    int node = t >> 5, lane = t & 31;
    if (node >= N) return;
    float4 s4 = *(const float4*)(g_s + node * 4);
    float ix = __fdividef(1.f, s4.x), iy = __fdividef(1.f, s4.y);
    float iz = __fdividef(1.f, s4.z), iw = __fdividef(1.f, s4.w);
    __half* p = g_Zph + (size_t)node * OH + lane * 4;
    uint2 z = *(uint2*)p;
    float2 lo = __half22float2(*reinterpret_cast<__half2*>(&z.x));
    float2 hi = __half22float2(*reinterpret_cast<__half2*>(&z.y));
    lo.x *= ix; lo.y *= iy; hi.x *= iz; hi.y *= iw;
    __half2 h0 = __floats2half2_rn(lo.x, lo.y);
    __half2 h1 = __floats2half2_rn(hi.x, hi.y);
    *(uint2*)p = make_uint2(*reinterpret_cast<unsigned*>(&h0), *reinterpret_cast<unsigned*>(&h1));
}

// ---- gather-reduce: one warp per node, 4x unrolled -------------------------------------------
__global__ void k_gather(float* __restrict__ out, int N) {
    int gw = (blockIdx.x * blockDim.x + threadIdx.x) >> 5;
    int lane = threadIdx.x & 31;
    if (gw >= N) return;
    int beg = g_off[gw], end = g_off[gw + 1];
    float4 acc = make_float4(0.f, 0.f, 0.f, 0.f);
    const __half* zb = g_Zph;
    int j = beg;
    for (; j + 3 < end; j += 4) {
        int4 s0 = g_slot[j];
        int4 s1 = g_slot[j + 1];
        int4 s2 = g_slot[j + 2];
        int4 s3 = g_slot[j + 3];
        uint2 z0 = *(const uint2*)(zb + (size_t)s0.x * OH + lane * 4);
        uint2 z1 = *(const uint2*)(zb + (size_t)s1.x * OH + lane * 4);
        uint2 z2 = *(const uint2*)(zb + (size_t)s2.x * OH + lane * 4);
        uint2 z3 = *(const uint2*)(zb + (size_t)s3.x * OH + lane * 4);
#define ACC(S, Z0, Z1)                                                    \
        {                                                                 \
            float2 e01 = __half22float2(*reinterpret_cast<__half2*>(&S.y));\
            float2 e23 = __half22float2(*reinterpret_cast<__half2*>(&S.z));\
            float2 a0 = __half22float2(*reinterpret_cast<__half2*>(&Z0)); \
            float2 a1 = __half22float2(*reinterpret_cast<__half2*>(&Z1)); \
            acc.x += e01.x * a0.x;  acc.y += e01.y * a0.y;                \
            acc.z += e23.x * a1.x;  acc.w += e23.y * a1.y;                \
        }
        ACC(s0, z0.x, z0.y); ACC(s1, z1.x, z1.y);
        ACC(s2, z2.x, z2.y); ACC(s3, z3.x, z3.y);
    }
    for (; j < end; j++) {
        int4 s0 = g_slot[j];
        uint2 z0 = *(const uint2*)(zb + (size_t)s0.x * OH + lane * 4);
        ACC(s0, z0.x, z0.y);
    }
#undef ACC
    *(float4*)(out + (size_t)gw * OH + lane * 4) = acc;
}

// ---- second stream for capture fork ------------------------------------------------------------
struct StreamHolder {
    cudaStream_t s2 = nullptr;
    cudaEvent_t evF = nullptr, evJ = nullptr;
    bool ok = false;
    StreamHolder() {
        ok = (cudaStreamCreateWithFlags(&s2, cudaStreamNonBlocking) == cudaSuccess) &&
             (cudaEventCreateWithFlags(&evF, cudaEventDisableTiming) == cudaSuccess) &&
             (cudaEventCreateWithFlags(&evJ, cudaEventDisableTiming) == cudaSuccess);
    }
};
static StreamHolder g_sh;

// ---- launch --------------------------------------------------------------------------------------
extern "C" void kernel_launch(void* const* d_in, const int* in_sizes, int n_in,
                              void* d_out, int out_size) {
    const void*  idx = d_in[0];
    const float* Z   = (const float*)d_in[2];
    const float* W   = (const float*)d_in[3];
    const float* b   = (const float*)d_in[4];
    const float* al  = (const float*)d_in[5];
    const float* ar  = (const float*)d_in[6];
    float* out = (float*)d_out;

    int E = in_sizes[0] / 2;
    int N = in_sizes[2] / 128;
    int nb = (N + 1023) / 1024;
    int eb = (E + 255) / 256;

    k_detect<<<1, 512>>>((const int*)idx);

    bool fork = g_sh.ok;
    cudaStream_t sb = fork ? g_sh.s2 : (cudaStream_t)0;
    if (fork) {
        cudaEventRecord(g_sh.evF, 0);
        cudaStreamWaitEvent(sb, g_sh.evF, 0);
    }
    // index-side chain
    k_init <<<256, 256, 0, sb>>>(N);
    k_hist <<<eb, 256, 0, sb>>>(idx, E);
    k_scan1<<<nb, 256, 0, sb>>>(N);
    k_scan2<<<1, 1, 0, sb>>>(nb);
    k_scan3<<<nb, 256, 0, sb>>>(N, E);

    // feature-side GEMM (concurrent with index chain)
    cudaFuncSetAttribute(k_gemm_mma, cudaFuncAttributeMaxDynamicSharedMemorySize, GEMM_SMEM);
    k_gemm_mma<<<(N + 63) / 64, 256, GEMM_SMEM>>>(Z, W, b, al, ar, N);

    if (fork) {
        cudaEventRecord(g_sh.evJ, sb);
        cudaStreamWaitEvent(0, g_sh.evJ, 0);
    }

    k_fused<<<eb, 256>>>(idx, E);
    k_scale<<<(N * 32 + 255) / 256, 256>>>(N);
    k_gather<<<(N * 32 + 255) / 256, 256>>>(out, N);
}